// round 15
// baseline (speedup 1.0000x reference)
#include <cuda_runtime.h>
#include <cuda_fp16.h>
#include <math.h>
#include <stdint.h>

// ---------------------------------------------------------------------------
// Problem constants: N=100000 nodes, E=1600000 edges, dims 256 -> 128 -> 128.
// ---------------------------------------------------------------------------
#define NMAX 100000
#define EMAX 1600000
#define FDIM 128
#define SCAN_TB 1024
#define NSCAN_BLOCKS ((NMAX + SCAN_TB - 1) / SCAN_TB)   // 98

// packed degree/count: [63:40] = edge count, [39:0] = weight sum in 20.20 fixed
#define DC_CNT_SHIFT 40
#define DC_W_SCALE   1048576.0f           // 2^20
#define DC_W_MASK    ((1ULL << DC_CNT_SHIFT) - 1ULL)

// Scratch (static device globals; no runtime allocation).
__device__ unsigned long long g_degcnt[NMAX];
__device__ unsigned long long g_bstate[NSCAN_BLOCKS];  // lookback: (status<<32)|val
__device__ float  g_dinv  [NMAX];
__device__ int    g_rowptr[NMAX + 1];
__device__ int    g_cursor[NMAX];
__device__ int2   g_edge  [EMAX];    // CSR-by-dst: {src, coef-as-bits}
__device__ __half g_h     [(size_t)NMAX * FDIM];  // GEMM1 output (fp16)
__device__ __half g_h2    [(size_t)NMAX * FDIM];  // fused agg1+GEMM2 output (fp16)

// ---------------------------------------------------------------------------
// Init: packed deg/cnt to self-loop, zero lookback state.
// ---------------------------------------------------------------------------
__global__ void k_init(unsigned long long* dc, unsigned long long* bstate, int n) {
    int i = blockIdx.x * blockDim.x + threadIdx.x;
    if (i < n) dc[i] = (unsigned long long)(1u << 20);   // self-loop w=1.0, cnt=0
    if (i < NSCAN_BLOCKS) bstate[i] = 0ULL;
}

__global__ void k_deg_cnt(const int* __restrict__ dst, const float* __restrict__ w,
                          unsigned long long* dc, int E) {
    int e = blockIdx.x * blockDim.x + threadIdx.x;
    if (e < E) {
        unsigned long long inc =
            (1ULL << DC_CNT_SHIFT) +
            (unsigned long long)__float2uint_rn(w[e] * DC_W_SCALE);
        atomicAdd(&dc[dst[e]], inc);
    }
}

// ---------------------------------------------------------------------------
// Single-pass decoupled-lookback exclusive scan over counts.
// Writes rowptr, cursor, dinv, and rowptr[n]=E.
// ---------------------------------------------------------------------------
__global__ __launch_bounds__(SCAN_TB)
void k_scan_onepass(const unsigned long long* __restrict__ dc,
                    unsigned long long* __restrict__ bstate,
                    int* __restrict__ rowptr, int* __restrict__ cursor,
                    float* __restrict__ dinv, int n, int E) {
    __shared__ int wsum[32];
    __shared__ int s_prefix;
    const int tid = threadIdx.x, lane = tid & 31, wid = tid >> 5;
    const int bid = blockIdx.x;
    int i = bid * SCAN_TB + tid;

    unsigned long long p = (i < n) ? dc[i] : 0ULL;
    int v = (int)(p >> DC_CNT_SHIFT);
    int x = v;
#pragma unroll
    for (int d = 1; d < 32; d <<= 1) {
        int y = __shfl_up_sync(0xffffffffu, x, d);
        if (lane >= d) x += y;
    }
    if (lane == 31) wsum[wid] = x;
    __syncthreads();
    if (wid == 0) {
        int s = wsum[lane];
#pragma unroll
        for (int d = 1; d < 32; d <<= 1) {
            int y = __shfl_up_sync(0xffffffffu, s, d);
            if (lane >= d) s += y;
        }
        wsum[lane] = s;
    }
    __syncthreads();
    int woff = wid ? wsum[wid - 1] : 0;
    int local_excl = woff + x - v;
    int btotal = wsum[31];

    if (tid == 0) {
        int prefix = 0;
        if (bid == 0) {
            atomicExch(&bstate[0], (2ULL << 32) | (unsigned)btotal);
        } else {
            atomicExch(&bstate[bid], (1ULL << 32) | (unsigned)btotal);
            for (int j = bid - 1; j >= 0; ) {
                unsigned long long s;
                do { s = atomicAdd(&bstate[j], 0ULL); } while ((s >> 32) == 0);
                prefix += (int)(unsigned)s;
                if ((s >> 32) == 2ULL) break;
                j--;
            }
            atomicExch(&bstate[bid], (2ULL << 32) | (unsigned)(prefix + btotal));
        }
        s_prefix = prefix;
    }
    __syncthreads();

    if (i < n) {
        int r = s_prefix + local_excl;
        rowptr[i] = r;
        cursor[i] = r;
        float deg = (float)(p & DC_W_MASK) * (1.0f / DC_W_SCALE);
        dinv[i] = rsqrtf(deg);
    }
    if (bid == gridDim.x - 1 && tid == 0) rowptr[n] = E;
}

// Fill CSR slots; packs {src, coef} into one 8B record.
__global__ void k_fill(const int* __restrict__ src, const int* __restrict__ dst,
                       const float* __restrict__ w, const float* __restrict__ dinv,
                       int* cursor, int2* __restrict__ edge, int E) {
    int e = blockIdx.x * blockDim.x + threadIdx.x;
    if (e >= E) return;
    int s = src[e], d = dst[e];
    int pos = atomicAdd(&cursor[d], 1);
    float coef = dinv[s] * w[e] * dinv[d];
    edge[pos] = make_int2(s, __float_as_int(coef));
}

// ---------------------------------------------------------------------------
// Shared MMA helpers
// ---------------------------------------------------------------------------
#define APITCH 20      // GEMM1: A smem pitch per 16-K chunk
#define AP2    132     // fused kernel: full-K A pitch (128 + 4)
#define BPITCH 136

__device__ __forceinline__ uint32_t f2tf32(float x) {
    uint32_t r;
    asm("cvt.rna.tf32.f32 %0, %1;" : "=r"(r) : "f"(x));
    return r;
}

__device__ __forceinline__ void mma_tf32(float* c, const uint32_t* a,
                                         uint32_t b0, uint32_t b1) {
    asm volatile(
        "mma.sync.aligned.m16n8k8.row.col.f32.tf32.tf32.f32 "
        "{%0,%1,%2,%3}, {%4,%5,%6,%7}, {%8,%9}, {%0,%1,%2,%3};"
        : "+f"(c[0]), "+f"(c[1]), "+f"(c[2]), "+f"(c[3])
        : "r"(a[0]), "r"(a[1]), "r"(a[2]), "r"(a[3]), "r"(b0), "r"(b1));
}

__device__ __forceinline__ float gelu_erf(float x) {
    return 0.5f * x * (1.0f + erff(x * 0.70710678118654752440f));
}

// 4 halves at h[row*128 + lane*4] -> float4
__device__ __forceinline__ float4 load_h4(const __half* __restrict__ h,
                                          size_t row, int lane) {
    float2 raw = ((const float2*)(h + row * 128))[lane];   // 8B = 4 halves
    __half2 p0 = *(__half2*)&raw.x;
    __half2 p1 = *(__half2*)&raw.y;
    float2 f0 = __half22float2(p0);
    float2 f1 = __half22float2(p1);
    return make_float4(f0.x, f0.y, f1.x, f1.y);
}

// ---------------------------------------------------------------------------
// GEMM1: C[M,128] = A[M,K] @ B[K,128], fp32 A, epilogue stores fp16.
// CTA tile 128x128, BK=16, 8 warps, warp tile 32x64, m16n8k8, fp32 acc.
// ---------------------------------------------------------------------------
__global__ __launch_bounds__(256, 2)
void k_gemm_mma(const float* __restrict__ A, const float* __restrict__ B,
                __half* __restrict__ C, int M, int K) {
    __shared__ __align__(16) float As[2][128 * APITCH];
    __shared__ __align__(16) float Bs[2][16 * BPITCH];

    const int tid  = threadIdx.x;
    const int lane = tid & 31;
    const int wid  = tid >> 5;
    const int warp_m = wid & 3;
    const int warp_n = wid >> 2;
    const int gp = lane >> 2;
    const int tg = lane & 3;
    const int m0 = blockIdx.x * 128;

    float acc[2][8][4];
#pragma unroll
    for (int i = 0; i < 2; i++)
#pragma unroll
        for (int j = 0; j < 8; j++)
#pragma unroll
            for (int q = 0; q < 4; q++) acc[i][j][q] = 0.0f;

    float4 pa[2], pb[2];

    auto load_regs = [&](int k0) {
#pragma unroll
        for (int u = 0; u < 2; u++) {
            int idx = tid + u * 256;
            int ar  = idx >> 2;
            int aq  = idx & 3;
            pa[u] = (m0 + ar < M)
                  ? *(const float4*)(A + (size_t)(m0 + ar) * K + k0 + aq * 4)
                  : make_float4(0.f, 0.f, 0.f, 0.f);
            int kr = idx >> 5;
            int bq = idx & 31;
            pb[u] = *(const float4*)(B + (size_t)(k0 + kr) * 128 + bq * 4);
        }
    };

    auto store_smem = [&](int buf) {
#pragma unroll
        for (int u = 0; u < 2; u++) {
            int idx = tid + u * 256;
            int ar  = idx >> 2;
            int aq  = idx & 3;
            uint32_t* d = (uint32_t*)&As[buf][ar * APITCH + aq * 4];
            d[0] = f2tf32(pa[u].x); d[1] = f2tf32(pa[u].y);
            d[2] = f2tf32(pa[u].z); d[3] = f2tf32(pa[u].w);
            int kr = idx >> 5;
            int bq = idx & 31;
            uint32_t* e = (uint32_t*)&Bs[buf][kr * BPITCH + bq * 4];
            e[0] = f2tf32(pb[u].x); e[1] = f2tf32(pb[u].y);
            e[2] = f2tf32(pb[u].z); e[3] = f2tf32(pb[u].w);
        }
    };

    const int niter = K / 16;
    load_regs(0);
    store_smem(0);

    for (int it = 0; it < niter; it++) {
        if (it + 1 < niter) load_regs((it + 1) * 16);
        __syncthreads();
        const int buf = it & 1;
        const uint32_t* as = (const uint32_t*)&As[buf][0];
        const uint32_t* bs = (const uint32_t*)&Bs[buf][0];

#pragma unroll
        for (int kk = 0; kk < 16; kk += 8) {
            uint32_t af[2][4];
#pragma unroll
            for (int i = 0; i < 2; i++) {
                int mr = warp_m * 32 + i * 16 + gp;
                af[i][0] = as[(mr    ) * APITCH + kk + tg    ];
                af[i][1] = as[(mr + 8) * APITCH + kk + tg    ];
                af[i][2] = as[(mr    ) * APITCH + kk + tg + 4];
                af[i][3] = as[(mr + 8) * APITCH + kk + tg + 4];
            }
#pragma unroll
            for (int j = 0; j < 8; j++) {
                int nb = warp_n * 64 + j * 8 + gp;
                uint32_t b0 = bs[(kk + tg    ) * BPITCH + nb];
                uint32_t b1 = bs[(kk + tg + 4) * BPITCH + nb];
#pragma unroll
                for (int i = 0; i < 2; i++)
                    mma_tf32(acc[i][j], af[i], b0, b1);
            }
        }
        if (it + 1 < niter) store_smem((it + 1) & 1);
    }

#pragma unroll
    for (int i = 0; i < 2; i++) {
        int r0 = m0 + warp_m * 32 + i * 16 + gp;
        int r1 = r0 + 8;
#pragma unroll
        for (int j = 0; j < 8; j++) {
            int col = warp_n * 64 + j * 8 + tg * 2;
            if (r0 < M)
                *(__half2*)(C + (size_t)r0 * 128 + col) =
                    __floats2half2_rn(acc[i][j][0], acc[i][j][1]);
            if (r1 < M)
                *(__half2*)(C + (size_t)r1 * 128 + col) =
                    __floats2half2_rn(acc[i][j][2], acc[i][j][3]);
        }
    }
}

// ---------------------------------------------------------------------------
// FUSED agg1 + GEMM2:
// Phase A: each warp aggregates 16 nodes (round-11 inner loop: CSR gather of
//   fp16 h rows, fp32 acc, bias + erf-GELU), writing results as tf32 straight
//   into the GEMM A smem tile (a[] never touches global memory).
// Phase B: hout[tile] = A(smem,128xK128) @ W2(K128,128), streamed in 16-K
//   chunks, same m16n8k8 tf32 path; epilogue stores fp16 to hout (h2).
// smem: A 128*AP2 + B 2*16*BPITCH floats = 84,992 B -> 2 CTAs/SM.
// ---------------------------------------------------------------------------
#define FUSE_SMEM_BYTES ((128 * AP2 + 2 * 16 * BPITCH) * 4)

__global__ __launch_bounds__(256, 2)
void k_agg_gemm(const int* __restrict__ rowptr, const int2* __restrict__ edge,
                const __half* __restrict__ h, const float* __restrict__ dinv,
                const float* __restrict__ bias, const float* __restrict__ W2,
                __half* __restrict__ hout, int n) {
    extern __shared__ float sm[];
    uint32_t* as_u = (uint32_t*)sm;                  // A: 128 x AP2 (tf32 bits)
    float*    BsF  = sm + 128 * AP2;                 // B: 2 x 16 x BPITCH

    const int tid  = threadIdx.x;
    const int lane = tid & 31;
    const int wid  = tid >> 5;
    const int m0   = blockIdx.x * 128;

    // ---------------- Phase A: aggregate 16 nodes per warp ----------------
    for (int t = 0; t < 16; t++) {
        const int local = wid * 16 + t;
        const int node  = m0 + local;
        float4 acc = make_float4(0.f, 0.f, 0.f, 0.f);
        if (node < n) {
            int beg = __ldg(&rowptr[node]);
            int end = __ldg(&rowptr[node + 1]);
            float d = __ldg(&dinv[node]);
            float c = d * d;
            acc = load_h4(h, (size_t)node, lane);
            acc.x *= c; acc.y *= c; acc.z *= c; acc.w *= c;

            for (int base = beg; base < end; base += 32) {
                int m = end - base;
                if (m > 32) m = 32;
                int2 e_l = (lane < m) ? __ldg(&edge[base + lane]) : make_int2(0, 0);

                int j = 0;
                for (; j + 4 <= m; j += 4) {
                    int   s0 = __shfl_sync(0xffffffffu, e_l.x, j    );
                    int   s1 = __shfl_sync(0xffffffffu, e_l.x, j + 1);
                    int   s2 = __shfl_sync(0xffffffffu, e_l.x, j + 2);
                    int   s3 = __shfl_sync(0xffffffffu, e_l.x, j + 3);
                    float w0 = __int_as_float(__shfl_sync(0xffffffffu, e_l.y, j    ));
                    float w1 = __int_as_float(__shfl_sync(0xffffffffu, e_l.y, j + 1));
                    float w2 = __int_as_float(__shfl_sync(0xffffffffu, e_l.y, j + 2));
                    float w3 = __int_as_float(__shfl_sync(0xffffffffu, e_l.y, j + 3));
                    float4 v0 = load_h4(h, (size_t)s0, lane);
                    float4 v1 = load_h4(h, (size_t)s1, lane);
                    float4 v2 = load_h4(h, (size_t)s2, lane);
                    float4 v3 = load_h4(h, (size_t)s3, lane);
                    acc.x = fmaf(v0.x, w0, acc.x); acc.y = fmaf(v0.y, w0, acc.y);
                    acc.z = fmaf(v0.z, w0, acc.z); acc.w = fmaf(v0.w, w0, acc.w);
                    acc.x = fmaf(v1.x, w1, acc.x); acc.y = fmaf(v1.y, w1, acc.y);
                    acc.z = fmaf(v1.z, w1, acc.z); acc.w = fmaf(v1.w, w1, acc.w);
                    acc.x = fmaf(v2.x, w2, acc.x); acc.y = fmaf(v2.y, w2, acc.y);
                    acc.z = fmaf(v2.z, w2, acc.z); acc.w = fmaf(v2.w, w2, acc.w);
                    acc.x = fmaf(v3.x, w3, acc.x); acc.y = fmaf(v3.y, w3, acc.y);
                    acc.z = fmaf(v3.z, w3, acc.z); acc.w = fmaf(v3.w, w3, acc.w);
                }
                for (; j < m; j++) {
                    int   s = __shfl_sync(0xffffffffu, e_l.x, j);
                    float w = __int_as_float(__shfl_sync(0xffffffffu, e_l.y, j));
                    float4 v = load_h4(h, (size_t)s, lane);
                    acc.x = fmaf(v.x, w, acc.x);
                    acc.y = fmaf(v.y, w, acc.y);
                    acc.z = fmaf(v.z, w, acc.z);
                    acc.w = fmaf(v.w, w, acc.w);
                }
            }

            float4 bb = ((const float4*)bias)[lane];
            acc.x = gelu_erf(acc.x + bb.x);
            acc.y = gelu_erf(acc.y + bb.y);
            acc.z = gelu_erf(acc.z + bb.z);
            acc.w = gelu_erf(acc.w + bb.w);
        }
        uint32_t* p = &as_u[local * AP2 + lane * 4];
        p[0] = f2tf32(acc.x); p[1] = f2tf32(acc.y);
        p[2] = f2tf32(acc.z); p[3] = f2tf32(acc.w);
    }

    // ---------------- Phase B: GEMM over smem A, streamed W2 ----------------
    const int warp_m = wid & 3;
    const int warp_n = wid >> 2;
    const int gp = lane >> 2;
    const int tg = lane & 3;

    float acc2[2][8][4];
#pragma unroll
    for (int i = 0; i < 2; i++)
#pragma unroll
        for (int j = 0; j < 8; j++)
#pragma unroll
            for (int q = 0; q < 4; q++) acc2[i][j][q] = 0.0f;

    float4 pb[2];
    auto loadB = [&](int k0) {
#pragma unroll
        for (int u = 0; u < 2; u++) {
            int idx = tid + u * 256;
            int kr  = idx >> 5;
            int bq  = idx & 31;
            pb[u] = *(const float4*)(W2 + (size_t)(k0 + kr) * 128 + bq * 4);
        }
    };
    auto storeB = [&](int buf) {
#pragma unroll
        for (int u = 0; u < 2; u++) {
            int idx = tid + u * 256;
            int kr  = idx >> 5;
            int bq  = idx & 31;
            uint32_t* e = (uint32_t*)&BsF[buf * 16 * BPITCH + kr * BPITCH + bq * 4];
            e[0] = f2tf32(pb[u].x); e[1] = f2tf32(pb[u].y);
            e[2] = f2tf32(pb[u].z); e[3] = f2tf32(pb[u].w);
        }
    };

    loadB(0);
    storeB(0);

    for (int it = 0; it < 8; it++) {          // K = 128, 16 per iter
        if (it + 1 < 8) loadB((it + 1) * 16);
        __syncthreads();                       // also orders Phase A writes
        const uint32_t* bs = (const uint32_t*)&BsF[(it & 1) * 16 * BPITCH];
        const int koff = it * 16;

#pragma unroll
        for (int kk = 0; kk < 16; kk += 8) {
            uint32_t af[2][4];
#pragma unroll
            for (int i = 0; i < 2; i++) {
                int mr = warp_m * 32 + i * 16 + gp;
                af[i][0] = as_u[(mr    ) * AP2 + koff + kk + tg    ];
                af[i][1] = as_u[(mr + 8) * AP2 + koff + kk + tg    ];
                af[i][2] = as_u[(mr    ) * AP2 + koff + kk + tg + 4];
                af[i][3] = as_u[(mr + 8) * AP2 + koff + kk + tg + 4];
            }
#pragma unroll
            for (int j = 0; j < 8; j++) {
                int nb = warp_n * 64 + j * 8 + gp;
                uint32_t b0 = bs[(kk + tg    ) * BPITCH + nb];
                uint32_t b1 = bs[(kk + tg + 4) * BPITCH + nb];
#pragma unroll
                for (int i = 0; i < 2; i++)
                    mma_tf32(acc2[i][j], af[i], b0, b1);
            }
        }
        if (it + 1 < 8) storeB((it + 1) & 1);
    }

#pragma unroll
    for (int i = 0; i < 2; i++) {
        int r0 = m0 + warp_m * 32 + i * 16 + gp;
        int r1 = r0 + 8;
#pragma unroll
        for (int j = 0; j < 8; j++) {
            int col = warp_n * 64 + j * 8 + tg * 2;
            if (r0 < n)
                *(__half2*)(hout + (size_t)r0 * 128 + col) =
                    __floats2half2_rn(acc2[i][j][0], acc2[i][j][1]);
            if (r1 < n)
                *(__half2*)(hout + (size_t)r1 * 128 + col) =
                    __floats2half2_rn(acc2[i][j][2], acc2[i][j][3]);
        }
    }
}

// ---------------------------------------------------------------------------
// Final CSR aggregation + bias + erf-GELU (round-11 version, fp32 out).
// ---------------------------------------------------------------------------
__global__ __launch_bounds__(256, 8)
void k_aggregate_f(const int* __restrict__ rowptr, const int2* __restrict__ edge,
                   const __half* __restrict__ h, const float* __restrict__ dinv,
                   const float* __restrict__ bias, float* __restrict__ out, int n) {
    int node = (blockIdx.x * blockDim.x + threadIdx.x) >> 5;
    int lane = threadIdx.x & 31;
    if (node >= n) return;

    int beg = __ldg(&rowptr[node]);
    int end = __ldg(&rowptr[node + 1]);

    float d = __ldg(&dinv[node]);
    float c = d * d;
    float4 acc = load_h4(h, (size_t)node, lane);
    acc.x *= c; acc.y *= c; acc.z *= c; acc.w *= c;

    for (int base = beg; base < end; base += 32) {
        int m = end - base;
        if (m > 32) m = 32;
        int2 e_l = (lane < m) ? __ldg(&edge[base + lane]) : make_int2(0, 0);

        int j = 0;
        for (; j + 4 <= m; j += 4) {
            int   s0 = __shfl_sync(0xffffffffu, e_l.x, j    );
            int   s1 = __shfl_sync(0xffffffffu, e_l.x, j + 1);
            int   s2 = __shfl_sync(0xffffffffu, e_l.x, j + 2);
            int   s3 = __shfl_sync(0xffffffffu, e_l.x, j + 3);
            float w0 = __int_as_float(__shfl_sync(0xffffffffu, e_l.y, j    ));
            float w1 = __int_as_float(__shfl_sync(0xffffffffu, e_l.y, j + 1));
            float w2 = __int_as_float(__shfl_sync(0xffffffffu, e_l.y, j + 2));
            float w3 = __int_as_float(__shfl_sync(0xffffffffu, e_l.y, j + 3));
            float4 v0 = load_h4(h, (size_t)s0, lane);
            float4 v1 = load_h4(h, (size_t)s1, lane);
            float4 v2 = load_h4(h, (size_t)s2, lane);
            float4 v3 = load_h4(h, (size_t)s3, lane);
            acc.x = fmaf(v0.x, w0, acc.x); acc.y = fmaf(v0.y, w0, acc.y);
            acc.z = fmaf(v0.z, w0, acc.z); acc.w = fmaf(v0.w, w0, acc.w);
            acc.x = fmaf(v1.x, w1, acc.x); acc.y = fmaf(v1.y, w1, acc.y);
            acc.z = fmaf(v1.z, w1, acc.z); acc.w = fmaf(v1.w, w1, acc.w);
            acc.x = fmaf(v2.x, w2, acc.x); acc.y = fmaf(v2.y, w2, acc.y);
            acc.z = fmaf(v2.z, w2, acc.z); acc.w = fmaf(v2.w, w2, acc.w);
            acc.x = fmaf(v3.x, w3, acc.x); acc.y = fmaf(v3.y, w3, acc.y);
            acc.z = fmaf(v3.z, w3, acc.z); acc.w = fmaf(v3.w, w3, acc.w);
        }
        for (; j < m; j++) {
            int   s = __shfl_sync(0xffffffffu, e_l.x, j);
            float w = __int_as_float(__shfl_sync(0xffffffffu, e_l.y, j));
            float4 v = load_h4(h, (size_t)s, lane);
            acc.x = fmaf(v.x, w, acc.x);
            acc.y = fmaf(v.y, w, acc.y);
            acc.z = fmaf(v.z, w, acc.z);
            acc.w = fmaf(v.w, w, acc.w);
        }
    }

    float4 bb = ((const float4*)bias)[lane];
    acc.x = gelu_erf(acc.x + bb.x);
    acc.y = gelu_erf(acc.y + bb.y);
    acc.z = gelu_erf(acc.z + bb.z);
    acc.w = gelu_erf(acc.w + bb.w);
    ((float4*)(out + (size_t)node * 128))[lane] = acc;
}

// ---------------------------------------------------------------------------
// Launch. Graph topology:
//   default stream:  [fork] GEMM1 --------------[join] fusedAggGemm  agg2
//   side stream s2:  [fork] init degcnt scan1 fill [join]
// ---------------------------------------------------------------------------
extern "C" void kernel_launch(void* const* d_in, const int* in_sizes, int n_in,
                              void* d_out, int out_size) {
    const float* x  = (const float*)d_in[0];
    const int*   ei = (const int*)  d_in[1];
    const float* ew = (const float*)d_in[2];
    const float* W1 = (const float*)d_in[3];
    const float* b1 = (const float*)d_in[4];
    const float* W2 = (const float*)d_in[5];
    const float* b2 = (const float*)d_in[6];
    float* out = (float*)d_out;

    const int n  = out_size / FDIM;       // 100000
    const int K1 = in_sizes[0] / n;       // 256
    const int E  = in_sizes[2];           // 1600000
    const int* src = ei;
    const int* dst = ei + E;

    unsigned long long *dc, *bstate;
    float* dinv;
    __half *h, *h2;
    int *rowptr, *cursor;
    int2* edge;
    cudaGetSymbolAddress((void**)&dc,     g_degcnt);
    cudaGetSymbolAddress((void**)&bstate, g_bstate);
    cudaGetSymbolAddress((void**)&dinv,   g_dinv);
    cudaGetSymbolAddress((void**)&rowptr, g_rowptr);
    cudaGetSymbolAddress((void**)&cursor, g_cursor);
    cudaGetSymbolAddress((void**)&edge,   g_edge);
    cudaGetSymbolAddress((void**)&h,      g_h);
    cudaGetSymbolAddress((void**)&h2,     g_h2);

    cudaFuncSetAttribute(k_agg_gemm, cudaFuncAttributeMaxDynamicSharedMemorySize,
                         FUSE_SMEM_BYTES);

    const int TB = 256;
    const int nblk = (n + SCAN_TB - 1) / SCAN_TB;
    dim3 gn((n + TB - 1) / TB);
    dim3 ge((E + TB - 1) / TB);
    dim3 gagg(((size_t)n * 32 + TB - 1) / TB);
    dim3 ggemm((n + 127) / 128);

    cudaStream_t s2;
    cudaEvent_t evFork, evJoin;
    cudaStreamCreateWithFlags(&s2, cudaStreamNonBlocking);
    cudaEventCreateWithFlags(&evFork, cudaEventDisableTiming);
    cudaEventCreateWithFlags(&evJoin, cudaEventDisableTiming);

    cudaEventRecord(evFork, 0);
    cudaStreamWaitEvent(s2, evFork, 0);

    // --- side stream: CSR-by-dst build + normalization ---
    k_init        <<<gn, TB, 0, s2>>>(dc, bstate, n);
    k_deg_cnt     <<<ge, TB, 0, s2>>>(dst, ew, dc, E);
    k_scan_onepass<<<nblk, SCAN_TB, 0, s2>>>(dc, bstate, rowptr, cursor, dinv, n, E);
    k_fill        <<<ge, TB, 0, s2>>>(src, dst, ew, dinv, cursor, edge, E);
    cudaEventRecord(evJoin, s2);

    // --- default stream: GEMM1 runs concurrently with the CSR build ---
    k_gemm_mma<<<ggemm, 256>>>(x, W1, h, n, K1);

    cudaStreamWaitEvent(0, evJoin, 0);

    // --- fused agg1+GEMM2 (reads h, writes h2), then final aggregate ---
    k_agg_gemm   <<<ggemm, 256, FUSE_SMEM_BYTES>>>(rowptr, edge, h, dinv, b1,
                                                   W2, h2, n);
    k_aggregate_f<<<gagg, TB>>>(rowptr, edge, h2, dinv, b2, out, n);
}

// round 16
// speedup vs baseline: 1.1813x; 1.1813x over previous
#include <cuda_runtime.h>
#include <cuda_fp16.h>
#include <math.h>
#include <stdint.h>

// ---------------------------------------------------------------------------
// Problem constants: N=100000 nodes, E=1600000 edges, dims 256 -> 128 -> 128.
// ---------------------------------------------------------------------------
#define NMAX 100000
#define EMAX 1600000
#define FDIM 128
#define SCAN_TB 1024
#define NSCAN_BLOCKS ((NMAX + SCAN_TB - 1) / SCAN_TB)   // 98

// packed degree/count: [63:40] = edge count, [39:0] = weight sum in 20.20 fixed
#define DC_CNT_SHIFT 40
#define DC_W_SCALE   1048576.0f           // 2^20
#define DC_W_MASK    ((1ULL << DC_CNT_SHIFT) - 1ULL)

// Scratch (static device globals; no runtime allocation).
__device__ unsigned long long g_degcnt[NMAX];
__device__ unsigned long long g_bstate[NSCAN_BLOCKS];  // lookback: (status<<32)|val
__device__ float  g_dinv  [NMAX];
__device__ int    g_rowptr[NMAX + 1];
__device__ int    g_cursor[NMAX];
__device__ int2   g_edge  [EMAX];    // CSR-by-dst: {src, coef-as-bits} per slot
__device__ __half g_h     [(size_t)NMAX * FDIM];  // GEMM output (fp16)
__device__ __half g_a     [(size_t)NMAX * FDIM];  // layer-1 activation (fp16)

// ---------------------------------------------------------------------------
// Init: packed deg/cnt to self-loop, zero lookback state.
// ---------------------------------------------------------------------------
__global__ void k_init(unsigned long long* dc, unsigned long long* bstate, int n) {
    int i = blockIdx.x * blockDim.x + threadIdx.x;
    if (i < n) dc[i] = (unsigned long long)(1u << 20);   // self-loop w=1.0, cnt=0
    if (i < NSCAN_BLOCKS) bstate[i] = 0ULL;
}

__global__ void k_deg_cnt(const int* __restrict__ dst, const float* __restrict__ w,
                          unsigned long long* dc, int E) {
    int e = blockIdx.x * blockDim.x + threadIdx.x;
    if (e < E) {
        unsigned long long inc =
            (1ULL << DC_CNT_SHIFT) +
            (unsigned long long)__float2uint_rn(w[e] * DC_W_SCALE);
        atomicAdd(&dc[dst[e]], inc);
    }
}

// ---------------------------------------------------------------------------
// Single-pass decoupled-lookback exclusive scan over counts.
// Writes rowptr, cursor, dinv, and rowptr[n]=E. One kernel, 98 blocks —
// all co-resident on 148 SMs, so the lookback spin cannot deadlock.
// ---------------------------------------------------------------------------
__global__ __launch_bounds__(SCAN_TB)
void k_scan_onepass(const unsigned long long* __restrict__ dc,
                    unsigned long long* __restrict__ bstate,
                    int* __restrict__ rowptr, int* __restrict__ cursor,
                    float* __restrict__ dinv, int n, int E) {
    __shared__ int wsum[32];
    __shared__ int s_prefix;
    const int tid = threadIdx.x, lane = tid & 31, wid = tid >> 5;
    const int bid = blockIdx.x;
    int i = bid * SCAN_TB + tid;

    unsigned long long p = (i < n) ? dc[i] : 0ULL;
    int v = (int)(p >> DC_CNT_SHIFT);
    int x = v;
#pragma unroll
    for (int d = 1; d < 32; d <<= 1) {
        int y = __shfl_up_sync(0xffffffffu, x, d);
        if (lane >= d) x += y;
    }
    if (lane == 31) wsum[wid] = x;
    __syncthreads();
    if (wid == 0) {
        int s = wsum[lane];
#pragma unroll
        for (int d = 1; d < 32; d <<= 1) {
            int y = __shfl_up_sync(0xffffffffu, s, d);
            if (lane >= d) s += y;
        }
        wsum[lane] = s;
    }
    __syncthreads();
    int woff = wid ? wsum[wid - 1] : 0;
    int local_excl = woff + x - v;
    int btotal = wsum[31];

    // decoupled lookback (thread 0)
    if (tid == 0) {
        int prefix = 0;
        if (bid == 0) {
            atomicExch(&bstate[0], (2ULL << 32) | (unsigned)btotal);
        } else {
            atomicExch(&bstate[bid], (1ULL << 32) | (unsigned)btotal);
            for (int j = bid - 1; j >= 0; ) {
                unsigned long long s;
                do { s = atomicAdd(&bstate[j], 0ULL); } while ((s >> 32) == 0);
                prefix += (int)(unsigned)s;
                if ((s >> 32) == 2ULL) break;
                j--;
            }
            atomicExch(&bstate[bid], (2ULL << 32) | (unsigned)(prefix + btotal));
        }
        s_prefix = prefix;
    }
    __syncthreads();

    if (i < n) {
        int r = s_prefix + local_excl;
        rowptr[i] = r;
        cursor[i] = r;
        float deg = (float)(p & DC_W_MASK) * (1.0f / DC_W_SCALE);
        dinv[i] = rsqrtf(deg);
    }
    if (bid == gridDim.x - 1 && tid == 0) rowptr[n] = E;
}

// Fill CSR slots; packs {src, coef} into one 8B record.
__global__ void k_fill(const int* __restrict__ src, const int* __restrict__ dst,
                       const float* __restrict__ w, const float* __restrict__ dinv,
                       int* cursor, int2* __restrict__ edge, int E) {
    int e = blockIdx.x * blockDim.x + threadIdx.x;
    if (e >= E) return;
    int s = src[e], d = dst[e];
    int pos = atomicAdd(&cursor[d], 1);
    float coef = dinv[s] * w[e] * dinv[d];
    edge[pos] = make_int2(s, __float_as_int(coef));
}

// ---------------------------------------------------------------------------
// tf32 mma.sync GEMM: C[M,128] = A[M,K] @ B[K,128], epilogue stores fp16.
// A operand templated: float (layer 1) or __half (layer 2).
// CTA tile 128x128, BK=16, 8 warps, warp tile 32x64, m16n8k8, fp32 acc.
// ---------------------------------------------------------------------------
#define APITCH 20
#define BPITCH 136

__device__ __forceinline__ uint32_t f2tf32(float x) {
    uint32_t r;
    asm("cvt.rna.tf32.f32 %0, %1;" : "=r"(r) : "f"(x));
    return r;
}

__device__ __forceinline__ void mma_tf32(float* c, const uint32_t* a,
                                         uint32_t b0, uint32_t b1) {
    asm volatile(
        "mma.sync.aligned.m16n8k8.row.col.f32.tf32.tf32.f32 "
        "{%0,%1,%2,%3}, {%4,%5,%6,%7}, {%8,%9}, {%0,%1,%2,%3};"
        : "+f"(c[0]), "+f"(c[1]), "+f"(c[2]), "+f"(c[3])
        : "r"(a[0]), "r"(a[1]), "r"(a[2]), "r"(a[3]), "r"(b0), "r"(b1));
}

__device__ __forceinline__ float4 loadA4(const float* A, size_t off) {
    return *(const float4*)(A + off);
}
__device__ __forceinline__ float4 loadA4(const __half* A, size_t off) {
    uint2 raw = *(const uint2*)(A + off);             // 8B = 4 halves
    __half2 p0 = *(__half2*)&raw.x;
    __half2 p1 = *(__half2*)&raw.y;
    float2 f0 = __half22float2(p0);
    float2 f1 = __half22float2(p1);
    return make_float4(f0.x, f0.y, f1.x, f1.y);
}

template <typename AT>
__global__ __launch_bounds__(256, 2)
void k_gemm_mma(const AT* __restrict__ A, const float* __restrict__ B,
                __half* __restrict__ C, int M, int K) {
    __shared__ __align__(16) float As[2][128 * APITCH];
    __shared__ __align__(16) float Bs[2][16 * BPITCH];

    const int tid  = threadIdx.x;
    const int lane = tid & 31;
    const int wid  = tid >> 5;
    const int warp_m = wid & 3;
    const int warp_n = wid >> 2;
    const int gp = lane >> 2;
    const int tg = lane & 3;
    const int m0 = blockIdx.x * 128;

    float acc[2][8][4];
#pragma unroll
    for (int i = 0; i < 2; i++)
#pragma unroll
        for (int j = 0; j < 8; j++)
#pragma unroll
            for (int q = 0; q < 4; q++) acc[i][j][q] = 0.0f;

    float4 pa[2], pb[2];

    auto load_regs = [&](int k0) {
#pragma unroll
        for (int u = 0; u < 2; u++) {
            int idx = tid + u * 256;
            int ar  = idx >> 2;
            int aq  = idx & 3;
            pa[u] = (m0 + ar < M)
                  ? loadA4(A, (size_t)(m0 + ar) * K + k0 + aq * 4)
                  : make_float4(0.f, 0.f, 0.f, 0.f);
            int kr = idx >> 5;
            int bq = idx & 31;
            pb[u] = *(const float4*)(B + (size_t)(k0 + kr) * 128 + bq * 4);
        }
    };

    auto store_smem = [&](int buf) {
#pragma unroll
        for (int u = 0; u < 2; u++) {
            int idx = tid + u * 256;
            int ar  = idx >> 2;
            int aq  = idx & 3;
            uint32_t* d = (uint32_t*)&As[buf][ar * APITCH + aq * 4];
            d[0] = f2tf32(pa[u].x); d[1] = f2tf32(pa[u].y);
            d[2] = f2tf32(pa[u].z); d[3] = f2tf32(pa[u].w);
            int kr = idx >> 5;
            int bq = idx & 31;
            uint32_t* e = (uint32_t*)&Bs[buf][kr * BPITCH + bq * 4];
            e[0] = f2tf32(pb[u].x); e[1] = f2tf32(pb[u].y);
            e[2] = f2tf32(pb[u].z); e[3] = f2tf32(pb[u].w);
        }
    };

    const int niter = K / 16;
    load_regs(0);
    store_smem(0);

    for (int it = 0; it < niter; it++) {
        if (it + 1 < niter) load_regs((it + 1) * 16);
        __syncthreads();
        const int buf = it & 1;
        const uint32_t* as = (const uint32_t*)&As[buf][0];
        const uint32_t* bs = (const uint32_t*)&Bs[buf][0];

#pragma unroll
        for (int kk = 0; kk < 16; kk += 8) {
            uint32_t af[2][4];
#pragma unroll
            for (int i = 0; i < 2; i++) {
                int mr = warp_m * 32 + i * 16 + gp;
                af[i][0] = as[(mr    ) * APITCH + kk + tg    ];
                af[i][1] = as[(mr + 8) * APITCH + kk + tg    ];
                af[i][2] = as[(mr    ) * APITCH + kk + tg + 4];
                af[i][3] = as[(mr + 8) * APITCH + kk + tg + 4];
            }
#pragma unroll
            for (int j = 0; j < 8; j++) {
                int nb = warp_n * 64 + j * 8 + gp;
                uint32_t b0 = bs[(kk + tg    ) * BPITCH + nb];
                uint32_t b1 = bs[(kk + tg + 4) * BPITCH + nb];
#pragma unroll
                for (int i = 0; i < 2; i++)
                    mma_tf32(acc[i][j], af[i], b0, b1);
            }
        }
        if (it + 1 < niter) store_smem((it + 1) & 1);
    }

#pragma unroll
    for (int i = 0; i < 2; i++) {
        int r0 = m0 + warp_m * 32 + i * 16 + gp;
        int r1 = r0 + 8;
#pragma unroll
        for (int j = 0; j < 8; j++) {
            int col = warp_n * 64 + j * 8 + tg * 2;
            if (r0 < M)
                *(__half2*)(C + (size_t)r0 * 128 + col) =
                    __floats2half2_rn(acc[i][j][0], acc[i][j][1]);
            if (r1 < M)
                *(__half2*)(C + (size_t)r1 * 128 + col) =
                    __floats2half2_rn(acc[i][j][2], acc[i][j][3]);
        }
    }
}

// ---------------------------------------------------------------------------
// CSR aggregation + bias + erf-GELU, one warp per destination node.
// h is fp16; accumulation in fp32; output templated (fp16 mid / fp32 final).
// out[d,:] = gelu( h[d,:]*dinv[d]^2 + sum_e h[src_e,:]*coef_e + bias )
// ---------------------------------------------------------------------------
__device__ __forceinline__ float gelu_erf(float x) {
    return 0.5f * x * (1.0f + erff(x * 0.70710678118654752440f));
}

__device__ __forceinline__ float4 load_h4(const __half* __restrict__ h,
                                          size_t row, int lane) {
    float2 raw = ((const float2*)(h + row * 128))[lane];   // 8B = 4 halves
    __half2 p0 = *(__half2*)&raw.x;
    __half2 p1 = *(__half2*)&raw.y;
    float2 f0 = __half22float2(p0);
    float2 f1 = __half22float2(p1);
    return make_float4(f0.x, f0.y, f1.x, f1.y);
}

__device__ __forceinline__ void store_out(float* out, size_t row, int lane, float4 v) {
    ((float4*)(out + row * 128))[lane] = v;
}
__device__ __forceinline__ void store_out(__half* out, size_t row, int lane, float4 v) {
    float2 packed;
    *(__half2*)&packed.x = __floats2half2_rn(v.x, v.y);
    *(__half2*)&packed.y = __floats2half2_rn(v.z, v.w);
    ((float2*)(out + row * 128))[lane] = packed;
}

template <typename OutT>
__global__ __launch_bounds__(256, 8)
void k_aggregate(const int* __restrict__ rowptr, const int2* __restrict__ edge,
                 const __half* __restrict__ h, const float* __restrict__ dinv,
                 const float* __restrict__ bias, OutT* __restrict__ out, int n) {
    int node = (blockIdx.x * blockDim.x + threadIdx.x) >> 5;
    int lane = threadIdx.x & 31;
    if (node >= n) return;

    int beg = __ldg(&rowptr[node]);
    int end = __ldg(&rowptr[node + 1]);

    float d = __ldg(&dinv[node]);
    float c = d * d;
    float4 acc = load_h4(h, (size_t)node, lane);
    acc.x *= c; acc.y *= c; acc.z *= c; acc.w *= c;

    for (int base = beg; base < end; base += 32) {
        int m = end - base;
        if (m > 32) m = 32;
        int2 e_l = (lane < m) ? __ldg(&edge[base + lane]) : make_int2(0, 0);

        int j = 0;
        for (; j + 4 <= m; j += 4) {
            int   s0 = __shfl_sync(0xffffffffu, e_l.x, j    );
            int   s1 = __shfl_sync(0xffffffffu, e_l.x, j + 1);
            int   s2 = __shfl_sync(0xffffffffu, e_l.x, j + 2);
            int   s3 = __shfl_sync(0xffffffffu, e_l.x, j + 3);
            float w0 = __int_as_float(__shfl_sync(0xffffffffu, e_l.y, j    ));
            float w1 = __int_as_float(__shfl_sync(0xffffffffu, e_l.y, j + 1));
            float w2 = __int_as_float(__shfl_sync(0xffffffffu, e_l.y, j + 2));
            float w3 = __int_as_float(__shfl_sync(0xffffffffu, e_l.y, j + 3));
            float4 v0 = load_h4(h, (size_t)s0, lane);
            float4 v1 = load_h4(h, (size_t)s1, lane);
            float4 v2 = load_h4(h, (size_t)s2, lane);
            float4 v3 = load_h4(h, (size_t)s3, lane);
            acc.x = fmaf(v0.x, w0, acc.x); acc.y = fmaf(v0.y, w0, acc.y);
            acc.z = fmaf(v0.z, w0, acc.z); acc.w = fmaf(v0.w, w0, acc.w);
            acc.x = fmaf(v1.x, w1, acc.x); acc.y = fmaf(v1.y, w1, acc.y);
            acc.z = fmaf(v1.z, w1, acc.z); acc.w = fmaf(v1.w, w1, acc.w);
            acc.x = fmaf(v2.x, w2, acc.x); acc.y = fmaf(v2.y, w2, acc.y);
            acc.z = fmaf(v2.z, w2, acc.z); acc.w = fmaf(v2.w, w2, acc.w);
            acc.x = fmaf(v3.x, w3, acc.x); acc.y = fmaf(v3.y, w3, acc.y);
            acc.z = fmaf(v3.z, w3, acc.z); acc.w = fmaf(v3.w, w3, acc.w);
        }
        for (; j < m; j++) {
            int   s = __shfl_sync(0xffffffffu, e_l.x, j);
            float w = __int_as_float(__shfl_sync(0xffffffffu, e_l.y, j));
            float4 v = load_h4(h, (size_t)s, lane);
            acc.x = fmaf(v.x, w, acc.x);
            acc.y = fmaf(v.y, w, acc.y);
            acc.z = fmaf(v.z, w, acc.z);
            acc.w = fmaf(v.w, w, acc.w);
        }
    }

    float4 bb = ((const float4*)bias)[lane];
    acc.x = gelu_erf(acc.x + bb.x);
    acc.y = gelu_erf(acc.y + bb.y);
    acc.z = gelu_erf(acc.z + bb.z);
    acc.w = gelu_erf(acc.w + bb.w);
    store_out(out, (size_t)node, lane, acc);
}

// ---------------------------------------------------------------------------
// Launch. Graph topology (round-11 champion):
//   default stream:  [fork] GEMM1 --------------[join] agg1  GEMM2  agg2
//   side stream s2:  [fork] init degcnt scan1 fill [join]
// ---------------------------------------------------------------------------
extern "C" void kernel_launch(void* const* d_in, const int* in_sizes, int n_in,
                              void* d_out, int out_size) {
    const float* x  = (const float*)d_in[0];
    const int*   ei = (const int*)  d_in[1];
    const float* ew = (const float*)d_in[2];
    const float* W1 = (const float*)d_in[3];
    const float* b1 = (const float*)d_in[4];
    const float* W2 = (const float*)d_in[5];
    const float* b2 = (const float*)d_in[6];
    float* out = (float*)d_out;

    const int n  = out_size / FDIM;       // 100000
    const int K1 = in_sizes[0] / n;       // 256
    const int E  = in_sizes[2];           // 1600000
    const int* src = ei;
    const int* dst = ei + E;

    unsigned long long *dc, *bstate;
    float* dinv;
    __half *h, *a;
    int *rowptr, *cursor;
    int2* edge;
    cudaGetSymbolAddress((void**)&dc,     g_degcnt);
    cudaGetSymbolAddress((void**)&bstate, g_bstate);
    cudaGetSymbolAddress((void**)&dinv,   g_dinv);
    cudaGetSymbolAddress((void**)&rowptr, g_rowptr);
    cudaGetSymbolAddress((void**)&cursor, g_cursor);
    cudaGetSymbolAddress((void**)&edge,   g_edge);
    cudaGetSymbolAddress((void**)&h,      g_h);
    cudaGetSymbolAddress((void**)&a,      g_a);

    const int TB = 256;
    const int nblk = (n + SCAN_TB - 1) / SCAN_TB;
    dim3 gn((n + TB - 1) / TB);
    dim3 ge((E + TB - 1) / TB);
    dim3 gagg(((size_t)n * 32 + TB - 1) / TB);
    dim3 ggemm((n + 127) / 128);

    cudaStream_t s2;
    cudaEvent_t evFork, evJoin;
    cudaStreamCreateWithFlags(&s2, cudaStreamNonBlocking);
    cudaEventCreateWithFlags(&evFork, cudaEventDisableTiming);
    cudaEventCreateWithFlags(&evJoin, cudaEventDisableTiming);

    cudaEventRecord(evFork, 0);
    cudaStreamWaitEvent(s2, evFork, 0);

    // --- side stream: CSR-by-dst build + normalization (4 kernels) ---
    k_init        <<<gn, TB, 0, s2>>>(dc, bstate, n);
    k_deg_cnt     <<<ge, TB, 0, s2>>>(dst, ew, dc, E);
    k_scan_onepass<<<nblk, SCAN_TB, 0, s2>>>(dc, bstate, rowptr, cursor, dinv, n, E);
    k_fill        <<<ge, TB, 0, s2>>>(src, dst, ew, dinv, cursor, edge, E);
    cudaEventRecord(evJoin, s2);

    // --- default stream: GEMM1 runs concurrently with the CSR build ---
    k_gemm_mma<float><<<ggemm, 256>>>(x, W1, h, n, K1);

    cudaStreamWaitEvent(0, evJoin, 0);

    // --- layer 1 aggregate (fp16 out), layer 2 GEMM (fp16 A), final agg ---
    k_aggregate<__half><<<gagg, TB>>>(rowptr, edge, h, dinv, b1, a, n);
    k_gemm_mma<__half><<<ggemm, 256>>>(a, W2, h, n, FDIM);
    k_aggregate<float> <<<gagg, TB>>>(rowptr, edge, h, dinv, b2, out, n);
}